// round 6
// baseline (speedup 1.0000x reference)
#include <cuda_runtime.h>

// 8192x8192 fp32 input; 10 3x3 SAME convs; 4 2x2 maxpools.
// Stages: [conv,conv,pool] x2 then [conv,conv,conv,pool] x2.

__device__ float g_buf0[4096u * 4096u];
__device__ float g_buf1[2048u * 2048u];
__device__ float g_buf2[1024u * 1024u];

#define NT 320                 // threads per block (10 warps)
#define BD 72                  // smem buffer dim (stride), 16B-aligned rows
#define STRIPS 17              // 17 x 17 threads x (4x4 px) cover 68x68
#define NACT (STRIPS * STRIPS) // 289 active conv threads

// Load 8 consecutive floats (two aligned float4) from smem.
__device__ __forceinline__ void ld8(float* d, const float* p) {
    float4 a = *(const float4*)(p);
    float4 b = *(const float4*)(p + 4);
    d[0] = a.x; d[1] = a.y; d[2] = a.z; d[3] = a.w;
    d[4] = b.x; d[5] = b.y; d[6] = b.z; d[7] = b.w;
}

__device__ __forceinline__ void conv_row(float v[4], const float* r0,
                                         const float* r1, const float* r2,
                                         const float k[9]) {
#pragma unroll
    for (int q = 0; q < 4; ++q) {
        v[q] = r0[q] * k[0] + r0[q + 1] * k[1] + r0[q + 2] * k[2]
             + r1[q] * k[3] + r1[q + 1] * k[4] + r1[q + 2] * k[5]
             + r2[q] * k[6] + r2[q + 1] * k[7] + r2[q + 2] * k[8];
    }
}

// One conv layer with shifted-origin output: dst[r][x] = conv(src)[r+1][x+1].
// Every layer therefore reads ld8 at col 4s (window offset 0) and stores an
// aligned float4 at col 4s. EDGE: re-apply SAME zero padding at the image
// boundary; dst(r,x) has absolute coords (ey0+r, ex0+x).
template <bool EDGE>
__device__ __forceinline__ void layer_mid(const float* __restrict__ src,
                                          float* __restrict__ dst,
                                          const float k[9], int s, int g,
                                          int ey0, int ex0, unsigned uw) {
    const float* sp = src + (4 * g) * BD + 4 * s;
    float r[3][8];
    ld8(r[0], sp);
    ld8(r[1], sp + BD);
#pragma unroll
    for (int j = 0; j < 4; ++j) {
        ld8(r[(j + 2) % 3], sp + (2 + j) * BD);
        float v[4];
        conv_row(v, r[j % 3], r[(j + 1) % 3], r[(j + 2) % 3], k);
        if (EDGE) {
            const bool rok = (unsigned)(ey0 + 4 * g + j) < uw;
#pragma unroll
            for (int q = 0; q < 4; ++q)
                if (!(rok && ((unsigned)(ex0 + 4 * s + q) < uw))) v[q] = 0.0f;
        }
        *(float4*)(dst + (4 * g + j) * BD + 4 * s) =
            make_float4(v[0], v[1], v[2], v[3]);
    }
}

// Last conv layer fused with 2x2 maxpool (interior blocks; s,g < 16).
// Thread's 4x4 output block is pool-aligned -> 2x2 pooled px -> direct STG.
__device__ __forceinline__ void layer_last_pool(const float* __restrict__ src,
                                                float* __restrict__ out,
                                                int outW, const float k[9],
                                                int s, int g, int oy, int ox) {
    const float* sp = src + (4 * g) * BD + 4 * s;
    float r[3][8];
    ld8(r[0], sp);
    ld8(r[1], sp + BD);
    float p[2][2];
#pragma unroll
    for (int j = 0; j < 4; ++j) {
        ld8(r[(j + 2) % 3], sp + (2 + j) * BD);
        float v[4];
        conv_row(v, r[j % 3], r[(j + 1) % 3], r[(j + 2) % 3], k);
        const int pr = j >> 1;
        float m0 = fmaxf(v[0], v[1]);
        float m1 = fmaxf(v[2], v[3]);
        if ((j & 1) == 0) { p[pr][0] = m0; p[pr][1] = m1; }
        else             { p[pr][0] = fmaxf(p[pr][0], m0);
                           p[pr][1] = fmaxf(p[pr][1], m1); }
    }
    float* op = out + (long)(oy + 2 * g) * outW + (ox + 2 * s);
    *(float2*)op = make_float2(p[0][0], p[0][1]);
    *(float2*)(op + outW) = make_float2(p[1][0], p[1][1]);
}

// Fused stage: K 3x3 convs (SAME at image boundary) + 2x2 maxpool.
// Block -> 32x32 pooled tile (64x64 pre-pool). EXT = 64 + 2K loaded extent.
template <int K>
__global__ __launch_bounds__(NT, 4)
void stage_kernel(const float* __restrict__ in, int inW,
                  float* __restrict__ out, int outW,
                  const float* __restrict__ w0,
                  const float* __restrict__ w1,
                  const float* __restrict__ w2) {
    constexpr int EXT = 64 + 2 * K;
    __shared__ float bufA[BD * BD];
    __shared__ float bufB[BD * BD];
    __shared__ float wts[27];

    const int tid = threadIdx.x;
    if (tid < K * 9) {
        const float* wp = (tid < 9) ? w0 : ((tid < 18) ? w1 : w2);
        wts[tid] = wp[tid % 9];
    }

    const int gx0 = blockIdx.x * 64 - K;
    const int gy0 = blockIdx.y * 64 - K;
    const unsigned uw = (unsigned)inW;  // square image
    const bool edge = (gx0 < 0) || (gy0 < 0) ||
                      (gx0 + EXT > inW) || (gy0 + EXT > inW);

    // Zero bufB (rim must be finite; interior of it gets overwritten).
    for (int i = tid; i < BD * BD / 4; i += NT)
        ((float4*)bufB)[i] = make_float4(0.f, 0.f, 0.f, 0.f);

    // Load input region into bufA (zero outside EXT / outside image).
    if (!edge && K == 2) {
        // Interior, K=2: gx0 is even -> aligned float2 global loads.
        if (tid < 288) {
            const int tc = tid % 36;            // float2 column
            const int tr = tid / 36;            // 8 concurrent rows
            const float* gp = in + (long)(gy0 + tr) * inW + gx0 + 2 * tc;
            const bool colin = (tc <= 33);      // cols < 68
#pragma unroll
            for (int r = tr; r < BD; r += 8, gp += 8L * inW) {
                float2 v = make_float2(0.f, 0.f);
                if (colin && r < EXT) v = *(const float2*)gp;
                *(float2*)&bufA[r * BD + 2 * tc] = v;
            }
        }
    } else {
        for (int i = tid; i < BD * BD; i += NT) {
            int r = i / BD, c = i - r * BD;
            float v = 0.0f;
            if (r < EXT && c < EXT) {
                int gy = gy0 + r, gx = gx0 + c;
                if (!edge || ((unsigned)gy < uw && (unsigned)gx < uw))
                    v = in[(long)gy * inW + gx];
            }
            bufA[i] = v;
        }
    }
    __syncthreads();

    const bool active = tid < NACT;
    const int s = tid % STRIPS;
    const int g = tid / STRIPS;
    const int ox = blockIdx.x * 32, oy = blockIdx.y * 32;

    float k[9];
    float* src = bufA;
    float* dst = bufB;

    // ---- layers 0 .. K-2 (to smem) ----
#pragma unroll
    for (int c = 0; c < K - 1; ++c) {
        if (active) {
#pragma unroll
            for (int m = 0; m < 9; ++m) k[m] = wts[c * 9 + m];
            if (edge) layer_mid<true >(src, dst, k, s, g,
                                       gy0 + c + 1, gx0 + c + 1, uw);
            else      layer_mid<false>(src, dst, k, s, g, 0, 0, uw);
        }
        __syncthreads();
        float* t = src; src = dst; dst = t;
    }

    // ---- last layer ----
    if (!edge) {
        if (s < 16 && g < 16 && active) {
#pragma unroll
            for (int m = 0; m < 9; ++m) k[m] = wts[(K - 1) * 9 + m];
            layer_last_pool(src, out, outW, k, s, g, oy, ox);
        }
        // no further smem use; no sync needed before exit
    } else {
        if (active) {
#pragma unroll
            for (int m = 0; m < 9; ++m) k[m] = wts[(K - 1) * 9 + m];
            layer_mid<true>(src, dst, k, s, g, gy0 + K, gx0 + K, uw);
        }
        __syncthreads();
        // Pool over dst [0,64)^2 (shifted coords: buf 0 == abs blockIdx*64).
        for (int i = tid; i < 1024; i += NT) {
            int py = i >> 5, px = i & 31;
            const float* p = dst + (2 * py) * BD + 2 * px;
            float m = fmaxf(fmaxf(p[0], p[1]), fmaxf(p[BD], p[BD + 1]));
            out[(long)(oy + py) * outW + ox + px] = m;
        }
    }
}

extern "C" void kernel_launch(void* const* d_in, const int* in_sizes, int n_in,
                              void* d_out, int out_size) {
    const float* x = (const float*)d_in[0];
    const float* w[10];
    for (int i = 0; i < 10; ++i) w[i] = (const float*)d_in[1 + i];

    float *b0, *b1, *b2;
    cudaGetSymbolAddress((void**)&b0, g_buf0);
    cudaGetSymbolAddress((void**)&b1, g_buf1);
    cudaGetSymbolAddress((void**)&b2, g_buf2);

    float* outp = (float*)d_out;

    stage_kernel<2><<<dim3(128, 128), NT>>>(x,  8192, b0,  4096, w[0], w[1], nullptr);
    stage_kernel<2><<<dim3(64, 64),   NT>>>(b0, 4096, b1,  2048, w[2], w[3], nullptr);
    stage_kernel<3><<<dim3(32, 32),   NT>>>(b1, 2048, b2,  1024, w[4], w[5], w[6]);
    stage_kernel<3><<<dim3(16, 16),   NT>>>(b2, 1024, outp, 512, w[7], w[8], w[9]);
}